// round 10
// baseline (speedup 1.0000x reference)
#include <cuda_runtime.h>
#include <cuda_bf16.h>
#include <mma.h>

using namespace nvcuda;

// Problem constants
#define NC     64          // channels
#define SS     3136        // 56*56
#define NIMG   128
#define MTOT   (NIMG*SS)   // 401408
#define KT     64          // s-tile width
#define TILES  (NIMG*49)   // 6272 tiles of 64 columns
#define GRID   444         // persistent grid: 148 SMs x 3 CTA/SM = one wave
#define BPITCH 72          // bf16 smem pitch (mult of 8 elems = 16B)
#define SPITCH 40          // fp32 scratch pitch: 40 words -> conflict-free LDS.128
#define EPSF   1e-3f

// Scratch (static device globals: allocation-free)
__device__ float          g_partials[GRID][4160]; // 4096 gram + 64 channel sums
__device__ float          g_G[4160];
__device__ float          g_mean[NC];
__device__ __nv_bfloat16  g_E[NC*NC];             // wm - I, row-major [c_out][c_in]

// ---------------------------------------------------------------------------
// Kernel 1: partial Gram + channel sums. Persistent grid, 3 CTAs/SM.
// Double-buffered bf16 tile, ONE __syncthreads per tile; next-tile LDG is
// issued AFTER the MMA so registers stay low (CTA-level overlap hides it).
// ---------------------------------------------------------------------------
__global__ __launch_bounds__(256, 3) void gram_kernel(const float* __restrict__ X) {
    __shared__ __nv_bfloat16 tb[2][NC * BPITCH];
    __shared__ float ssum[NC];

    const int t = threadIdx.x, b = blockIdx.x;
    const int warp = t >> 5;
    const int row = t >> 2;          // channel row 0..63
    const int c4  = (t & 3) * 4;     // first float4 index

    const int r0 = (warp >> 1) * 16;     // output row block (strip)
    const int q0 = (warp & 1) * 32;      // output col base

    wmma::fragment<wmma::accumulator, 16, 16, 16, float> acc[2];
    wmma::fill_fragment(acc[0], 0.0f);
    wmma::fill_fragment(acc[1], 0.0f);

    float lsum = 0.0f;

    // prologue: tile b -> tb[0]
    {
        const int n  = b / 49;
        const int s0 = (b % 49) * KT;
        const float4* src = (const float4*)(X + (size_t)n * NC * SS + (size_t)row * SS + s0);
        #pragma unroll
        for (int j = 0; j < 4; ++j) {
            float4 v = src[c4 + j];
            lsum += v.x + v.y + v.z + v.w;
            __nv_bfloat162* dst = (__nv_bfloat162*)&tb[0][row * BPITCH + (c4 + j) * 4];
            dst[0] = __floats2bfloat162_rn(v.x, v.y);
            dst[1] = __floats2bfloat162_rn(v.z, v.w);
        }
    }
    __syncthreads();

    int buf = 0;
    for (int T = b; T < TILES; T += GRID, buf ^= 1) {
        #pragma unroll
        for (int k = 0; k < 4; ++k) {
            wmma::fragment<wmma::matrix_a, 16, 16, 16, __nv_bfloat16, wmma::row_major> fa;
            wmma::fragment<wmma::matrix_b, 16, 16, 16, __nv_bfloat16, wmma::col_major> fb0, fb1;
            wmma::load_matrix_sync(fa,  &tb[buf][r0 * BPITCH + k * 16], BPITCH);
            wmma::load_matrix_sync(fb0, &tb[buf][q0 * BPITCH + k * 16], BPITCH);
            wmma::load_matrix_sync(fb1, &tb[buf][(q0 + 16) * BPITCH + k * 16], BPITCH);
            wmma::mma_sync(acc[0], fa, fb0, acc[0]);
            wmma::mma_sync(acc[1], fa, fb1, acc[1]);
        }

        // load + publish next tile (after MMA: regs reused, other CTAs overlap)
        const int Tn = T + GRID;
        if (Tn < TILES) {
            const int n  = Tn / 49;
            const int s0 = (Tn % 49) * KT;
            const float4* src = (const float4*)(X + (size_t)n * NC * SS + (size_t)row * SS + s0);
            #pragma unroll
            for (int j = 0; j < 4; ++j) {
                float4 v = src[c4 + j];
                lsum += v.x + v.y + v.z + v.w;
                __nv_bfloat162* dst = (__nv_bfloat162*)&tb[buf ^ 1][row * BPITCH + (c4 + j) * 4];
                dst[0] = __floats2bfloat162_rn(v.x, v.y);
                dst[1] = __floats2bfloat162_rn(v.z, v.w);
            }
        }
        __syncthreads();
    }

    lsum += __shfl_down_sync(0xffffffffu, lsum, 2);
    lsum += __shfl_down_sync(0xffffffffu, lsum, 1);
    if ((t & 3) == 0) ssum[row] = lsum;
    __syncthreads();

    wmma::store_matrix_sync(&g_partials[b][r0 * 64 + q0],      acc[0], 64, wmma::mem_row_major);
    wmma::store_matrix_sync(&g_partials[b][r0 * 64 + q0 + 16], acc[1], 64, wmma::mem_row_major);
    if (t < NC) g_partials[b][4096 + t] = ssum[t];
}

// ---------------------------------------------------------------------------
// Kernel 2: reduce GRID partials -> g_G  (float4 vectorized)
// ---------------------------------------------------------------------------
__global__ __launch_bounds__(256) void reduce_kernel() {
    const int i4 = blockIdx.x * blockDim.x + threadIdx.x;
    if (i4 < 1040) {  // 4160/4
        float4 s = make_float4(0.f, 0.f, 0.f, 0.f);
        #pragma unroll 4
        for (int b = 0; b < GRID; ++b) {
            float4 v = ((const float4*)g_partials[b])[i4];
            s.x += v.x; s.y += v.y; s.z += v.z; s.w += v.w;
        }
        ((float4*)g_G)[i4] = s;
    }
}

// ---------------------------------------------------------------------------
// Kernel 3: single-block stats: sigma -> Taylor inverse-sqrt -> E = wm - I (bf16)
// ---------------------------------------------------------------------------
__global__ __launch_bounds__(256) void stats_kernel() {
    __shared__ float sP[4096];
    __shared__ float sQ[4096];
    __shared__ float smean[NC];
    __shared__ float sMu, sRs;

    const int t = threadIdx.x;
    const float invm = 1.0f / (float)MTOT;

    if (t < NC) {
        float mn = g_G[4096 + t] * invm;
        smean[t] = mn;
        g_mean[t] = mn;
    }
    __syncthreads();

    for (int i = t; i < 4096; i += 256) {
        int r = i >> 6, c = i & 63;
        sP[i] = g_G[i] * invm - smean[r] * smean[c] + ((r == c) ? EPSF : 0.0f);
    }
    __syncthreads();

    if (t == 0) {
        float tr = 0.0f;
        for (int i = 0; i < NC; ++i) tr += sP[i * 65];
        float mu = tr / (float)NC;
        sMu = mu;
        float rs = rsqrtf(mu);
        rs = rs * (1.5f - 0.5f * mu * rs * rs);
        sRs = rs;
    }
    __syncthreads();

    const float invmu = 1.0f / sMu;
    for (int i = t; i < 4096; i += 256) {
        int r = i >> 6, c = i & 63;
        sP[i] = sP[i] * invmu - ((r == c) ? 1.0f : 0.0f);
    }
    __syncthreads();

    const int r0 = (t >> 4) * 4;
    const int c0 = (t & 15) * 4;
    {
        float a[4][4] = {};
        for (int k = 0; k < 64; ++k) {
            float pa[4], pb[4];
            #pragma unroll
            for (int i = 0; i < 4; ++i) pa[i] = sP[(r0 + i) * 64 + k];
            #pragma unroll
            for (int j = 0; j < 4; ++j) pb[j] = sP[k * 64 + c0 + j];
            #pragma unroll
            for (int i = 0; i < 4; ++i)
                #pragma unroll
                for (int j = 0; j < 4; ++j) a[i][j] += pa[i] * pb[j];
        }
        #pragma unroll
        for (int i = 0; i < 4; ++i)
            #pragma unroll
            for (int j = 0; j < 4; ++j) sQ[(r0 + i) * 64 + c0 + j] = a[i][j];
    }
    __syncthreads();

    const float rs = sRs;
    {
        float a[4][4] = {};  // Q@P block
        for (int k = 0; k < 64; ++k) {
            float pa[4], pb[4];
            #pragma unroll
            for (int i = 0; i < 4; ++i) pa[i] = sQ[(r0 + i) * 64 + k];
            #pragma unroll
            for (int j = 0; j < 4; ++j) pb[j] = sP[k * 64 + c0 + j];
            #pragma unroll
            for (int i = 0; i < 4; ++i)
                #pragma unroll
                for (int j = 0; j < 4; ++j) a[i][j] += pa[i] * pb[j];
        }
        #pragma unroll
        for (int i = 0; i < 4; ++i) {
            #pragma unroll
            for (int j = 0; j < 4; ++j) {
                int idx = (r0 + i) * 64 + (c0 + j);
                float dlt = (r0 + i == c0 + j) ? 1.0f : 0.0f;
                float wmh = dlt - 0.5f * sP[idx] + 0.375f * sQ[idx] - 0.3125f * a[i][j];
                g_E[idx] = __float2bfloat16(wmh * rs - dlt);
            }
        }
    }
}

// ---------------------------------------------------------------------------
// Kernel 4: whiten  out = xc + E @ xc   (persistent grid, 3 CTAs/SM)
//  - E fragments hoisted (loaded ONCE from g_E)
//  - warp-matched ownership; centered fp32 xc in registers across the MMA
//  - correction via warp-private scratch (__syncwarp only)
//  - double-buffered bf16 tile, ONE block barrier per tile
//  - next tile loaded into `cur` AFTER the epilogue (acc regs reused ->
//    low register count -> 3 CTAs/SM; CTA-level overlap hides the LDG)
// ---------------------------------------------------------------------------
__global__ __launch_bounds__(256, 3) void whiten_kernel(const float* __restrict__ X,
                                                        float* __restrict__ Y) {
    __shared__ __nv_bfloat16  tb[2][NC * BPITCH];      // bf16 centered tiles
    __shared__ float          scratch[8][16 * SPITCH]; // per-warp 16x32 corr
    __shared__ float          smean[NC];

    const int t = threadIdx.x, b = blockIdx.x;
    const int warp = t >> 5, lane = t & 31;

    if (t < NC) smean[t] = g_mean[t];
    __syncthreads();

    const int r0 = (warp >> 1) * 16;       // warp's output channel strip
    const int q0 = (warp & 1) * 32;        // warp's s base
    const int row  = r0 + (lane >> 1);     // this lane's channel row
    const int coff = q0 + (lane & 1) * 4;  // this lane's first float col (j adds 8j)
    const float mu = smean[row];

    // hoisted E fragments: loaded once, directly from global
    wmma::fragment<wmma::matrix_a, 16, 16, 16, __nv_bfloat16, wmma::row_major> fa[4];
    #pragma unroll
    for (int k = 0; k < 4; ++k)
        wmma::load_matrix_sync(fa[k], &g_E[r0 * 64 + k * 16], 64);

    const float* scp = &scratch[warp][(lane >> 1) * SPITCH + (lane & 1) * 4];

    // prologue: tile b -> centered regs + tb[0]
    float4 cur[4];
    {
        const int n  = b / 49;
        const int s0 = (b % 49) * KT;
        const float* src = X + (size_t)n * NC * SS + (size_t)row * SS + s0 + coff;
        #pragma unroll
        for (int j = 0; j < 4; ++j) {
            float4 v = *(const float4*)(src + 8 * j);
            v.x -= mu; v.y -= mu; v.z -= mu; v.w -= mu;
            cur[j] = v;
            __nv_bfloat162* dst = (__nv_bfloat162*)&tb[0][row * BPITCH + coff + 8 * j];
            dst[0] = __floats2bfloat162_rn(v.x, v.y);
            dst[1] = __floats2bfloat162_rn(v.z, v.w);
        }
    }
    __syncthreads();

    int buf = 0;
    for (int T = b; T < TILES; T += GRID, buf ^= 1) {
        const int n  = T / 49;
        const int s0 = (T % 49) * KT;

        // correction = E @ xc  (fa hoisted; only fb loads per k)
        wmma::fragment<wmma::accumulator, 16, 16, 16, float> acc0, acc1;
        wmma::fill_fragment(acc0, 0.0f);
        wmma::fill_fragment(acc1, 0.0f);
        #pragma unroll
        for (int k = 0; k < 4; ++k) {
            wmma::fragment<wmma::matrix_b, 16, 16, 16, __nv_bfloat16, wmma::row_major> fb0, fb1;
            wmma::load_matrix_sync(fb0, &tb[buf][(k * 16) * BPITCH + q0], BPITCH);
            wmma::load_matrix_sync(fb1, &tb[buf][(k * 16) * BPITCH + q0 + 16], BPITCH);
            wmma::mma_sync(acc0, fa[k], fb0, acc0);
            wmma::mma_sync(acc1, fa[k], fb1, acc1);
        }
        wmma::store_matrix_sync(&scratch[warp][0],  acc0, SPITCH, wmma::mem_row_major);
        wmma::store_matrix_sync(&scratch[warp][16], acc1, SPITCH, wmma::mem_row_major);
        __syncwarp();   // scratch visibility within the warp

        // epilogue (fully warp-local): out = xc(regs) + corr(scratch)
        {
            float* Yp = Y + (size_t)n * NC * SS + (size_t)row * SS + s0 + coff;
            #pragma unroll
            for (int j = 0; j < 4; ++j) {
                float4 c = *(const float4*)(scp + 8 * j);
                c.x += cur[j].x; c.y += cur[j].y; c.z += cur[j].z; c.w += cur[j].w;
                *(float4*)(Yp + 8 * j) = c;
            }
        }

        // load + center + publish next tile (acc regs dead -> reused here)
        const int Tn = T + GRID;
        if (Tn < TILES) {
            const int nn = Tn / 49;
            const int sn = (Tn % 49) * KT;
            const float* src = X + (size_t)nn * NC * SS + (size_t)row * SS + sn + coff;
            #pragma unroll
            for (int j = 0; j < 4; ++j) {
                float4 v = *(const float4*)(src + 8 * j);
                v.x -= mu; v.y -= mu; v.z -= mu; v.w -= mu;
                cur[j] = v;
                __nv_bfloat162* dst = (__nv_bfloat162*)&tb[buf ^ 1][row * BPITCH + coff + 8 * j];
                dst[0] = __floats2bfloat162_rn(v.x, v.y);
                dst[1] = __floats2bfloat162_rn(v.z, v.w);
            }
        }
        __syncthreads();   // tb[buf^1] published; tb[buf] fully consumed
    }
}

// ---------------------------------------------------------------------------
extern "C" void kernel_launch(void* const* d_in, const int* in_sizes, int n_in,
                              void* d_out, int out_size) {
    (void)in_sizes; (void)n_in; (void)out_size;
    const float* X = (const float*)d_in[0];
    float* Y = (float*)d_out;

    gram_kernel<<<GRID, 256>>>(X);
    reduce_kernel<<<5, 256>>>();
    stats_kernel<<<1, 256>>>();
    whiten_kernel<<<GRID, 256>>>(X, Y);
}

// round 11
// speedup vs baseline: 1.0529x; 1.0529x over previous
#include <cuda_runtime.h>
#include <cuda_bf16.h>
#include <mma.h>

using namespace nvcuda;

// Problem constants
#define NC     64          // channels
#define SS     3136        // 56*56
#define NIMG   128
#define MTOT   (NIMG*SS)   // 401408
#define KT     64          // s-tile width
#define TILES  (NIMG*49)   // 6272 tiles of 64 columns
#define GRID_G 296         // gram: one wave at 2 CTA/SM
#define GRID_W 444         // whiten: one wave at 3 CTA/SM
#define BPITCH 72          // bf16 smem pitch (mult of 8 elems = 16B)
#define SPITCH 40          // fp32 scratch pitch (whiten)
#define RPITCH 36          // fp32 reduction pitch (gram epilogue)
#define EPSF   1e-3f

// Scratch (static device globals: allocation-free)
__device__ float          g_partials[GRID_G][4160]; // 4096 gram + 64 channel sums
__device__ float          g_G[4160];
__device__ float          g_mean[NC];
__device__ __nv_bfloat16  g_E[NC*NC];               // wm - I, row-major

// ---------------------------------------------------------------------------
// Kernel 1: partial Gram + channel sums. Persistent one-wave grid (2 CTA/SM),
// register prefetch of next tile BEFORE the MMA (measured win), double-
// buffered bf16 tile, ONE __syncthreads per tile.
// Split-K warp layout: warp = (khalf, quadrant); each warp computes a 32x32
// output quadrant over half of K -> 8 fragment loads feed 8 MMAs per tile
// (was 12 loads / 8 MMAs). Cross-khalf reduction once at the end.
// ---------------------------------------------------------------------------
__global__ __launch_bounds__(256, 2) void gram_kernel(const float* __restrict__ X) {
    __shared__ __nv_bfloat16 tb[2][NC * BPITCH];
    __shared__ float sred[4][32 * RPITCH];   // khalf=1 warps' 32x32 partials
    __shared__ float ssum[NC];

    const int t = threadIdx.x, b = blockIdx.x;
    const int warp = t >> 5;
    const int row = t >> 2;          // loader: channel row 0..63
    const int c4  = (t & 3) * 4;     // loader: first float4 index

    const int khalf = warp >> 2;           // 0/1: K half
    const int quad  = warp & 3;            // output quadrant
    const int r0 = (quad >> 1) * 32;
    const int q0 = (quad & 1) * 32;
    const int k0 = khalf * 32;             // K offset within tile

    wmma::fragment<wmma::accumulator, 16, 16, 16, float> acc[2][2];
    #pragma unroll
    for (int i = 0; i < 2; ++i)
        #pragma unroll
        for (int j = 0; j < 2; ++j)
            wmma::fill_fragment(acc[i][j], 0.0f);

    float lsum = 0.0f;

    // prologue: tile b -> tb[0]
    {
        const int n  = b / 49;
        const int s0 = (b % 49) * KT;
        const float4* src = (const float4*)(X + (size_t)n * NC * SS + (size_t)row * SS + s0);
        #pragma unroll
        for (int j = 0; j < 4; ++j) {
            float4 v = src[c4 + j];
            lsum += v.x + v.y + v.z + v.w;
            __nv_bfloat162* dst = (__nv_bfloat162*)&tb[0][row * BPITCH + (c4 + j) * 4];
            dst[0] = __floats2bfloat162_rn(v.x, v.y);
            dst[1] = __floats2bfloat162_rn(v.z, v.w);
        }
    }
    __syncthreads();

    int buf = 0;
    for (int T = b; T < TILES; T += GRID_G, buf ^= 1) {
        const int Tn = T + GRID_G;
        const bool has = (Tn < TILES);

        // register prefetch of the next tile (in flight across the MMA)
        float4 w[4];
        if (has) {
            const int n  = Tn / 49;
            const int s0 = (Tn % 49) * KT;
            const float4* src = (const float4*)(X + (size_t)n * NC * SS + (size_t)row * SS + s0);
            #pragma unroll
            for (int j = 0; j < 4; ++j) w[j] = src[c4 + j];
        }

        #pragma unroll
        for (int k = 0; k < 2; ++k) {
            const int kk = k0 + k * 16;
            wmma::fragment<wmma::matrix_a, 16, 16, 16, __nv_bfloat16, wmma::row_major> fa0, fa1;
            wmma::fragment<wmma::matrix_b, 16, 16, 16, __nv_bfloat16, wmma::col_major> fb0, fb1;
            wmma::load_matrix_sync(fa0, &tb[buf][(r0)      * BPITCH + kk], BPITCH);
            wmma::load_matrix_sync(fa1, &tb[buf][(r0 + 16) * BPITCH + kk], BPITCH);
            wmma::load_matrix_sync(fb0, &tb[buf][(q0)      * BPITCH + kk], BPITCH);
            wmma::load_matrix_sync(fb1, &tb[buf][(q0 + 16) * BPITCH + kk], BPITCH);
            wmma::mma_sync(acc[0][0], fa0, fb0, acc[0][0]);
            wmma::mma_sync(acc[0][1], fa0, fb1, acc[0][1]);
            wmma::mma_sync(acc[1][0], fa1, fb0, acc[1][0]);
            wmma::mma_sync(acc[1][1], fa1, fb1, acc[1][1]);
        }

        // publish next tile into the other buffer
        if (has) {
            #pragma unroll
            for (int j = 0; j < 4; ++j) {
                lsum += w[j].x + w[j].y + w[j].z + w[j].w;
                __nv_bfloat162* dst = (__nv_bfloat162*)&tb[buf ^ 1][row * BPITCH + (c4 + j) * 4];
                dst[0] = __floats2bfloat162_rn(w[j].x, w[j].y);
                dst[1] = __floats2bfloat162_rn(w[j].z, w[j].w);
            }
        }
        __syncthreads();
    }

    // channel-sum reduce: 4 consecutive lanes share a row
    lsum += __shfl_down_sync(0xffffffffu, lsum, 2);
    lsum += __shfl_down_sync(0xffffffffu, lsum, 1);
    if ((t & 3) == 0) ssum[row] = lsum;

    // cross-khalf reduction: khalf=1 warps park their accs in smem
    if (khalf == 1) {
        #pragma unroll
        for (int i = 0; i < 2; ++i)
            #pragma unroll
            for (int j = 0; j < 2; ++j)
                wmma::store_matrix_sync(&sred[quad][(16 * i) * RPITCH + 16 * j],
                                        acc[i][j], RPITCH, wmma::mem_row_major);
    }
    __syncthreads();

    if (khalf == 0) {
        #pragma unroll
        for (int i = 0; i < 2; ++i) {
            #pragma unroll
            for (int j = 0; j < 2; ++j) {
                wmma::fragment<wmma::accumulator, 16, 16, 16, float> tmp;
                wmma::load_matrix_sync(tmp, &sred[quad][(16 * i) * RPITCH + 16 * j],
                                       RPITCH, wmma::mem_row_major);
                #pragma unroll
                for (int e = 0; e < tmp.num_elements; ++e)
                    acc[i][j].x[e] += tmp.x[e];
                wmma::store_matrix_sync(&g_partials[b][(r0 + 16 * i) * 64 + q0 + 16 * j],
                                        acc[i][j], 64, wmma::mem_row_major);
            }
        }
    }
    if (t < NC) g_partials[b][4096 + t] = ssum[t];
}

// ---------------------------------------------------------------------------
// Kernel 2: reduce GRID_G partials -> g_G  (float4 vectorized)
// ---------------------------------------------------------------------------
__global__ __launch_bounds__(256) void reduce_kernel() {
    const int i4 = blockIdx.x * blockDim.x + threadIdx.x;
    if (i4 < 1040) {  // 4160/4
        float4 s = make_float4(0.f, 0.f, 0.f, 0.f);
        #pragma unroll 4
        for (int b = 0; b < GRID_G; ++b) {
            float4 v = ((const float4*)g_partials[b])[i4];
            s.x += v.x; s.y += v.y; s.z += v.z; s.w += v.w;
        }
        ((float4*)g_G)[i4] = s;
    }
}

// ---------------------------------------------------------------------------
// Kernel 3: single-block stats: sigma -> Taylor inverse-sqrt -> E = wm - I (bf16)
// ---------------------------------------------------------------------------
__global__ __launch_bounds__(256) void stats_kernel() {
    __shared__ float sP[4096];
    __shared__ float sQ[4096];
    __shared__ float smean[NC];
    __shared__ float sMu, sRs;

    const int t = threadIdx.x;
    const float invm = 1.0f / (float)MTOT;

    if (t < NC) {
        float mn = g_G[4096 + t] * invm;
        smean[t] = mn;
        g_mean[t] = mn;
    }
    __syncthreads();

    for (int i = t; i < 4096; i += 256) {
        int r = i >> 6, c = i & 63;
        sP[i] = g_G[i] * invm - smean[r] * smean[c] + ((r == c) ? EPSF : 0.0f);
    }
    __syncthreads();

    if (t == 0) {
        float tr = 0.0f;
        for (int i = 0; i < NC; ++i) tr += sP[i * 65];
        float mu = tr / (float)NC;
        sMu = mu;
        float rs = rsqrtf(mu);
        rs = rs * (1.5f - 0.5f * mu * rs * rs);
        sRs = rs;
    }
    __syncthreads();

    const float invmu = 1.0f / sMu;
    for (int i = t; i < 4096; i += 256) {
        int r = i >> 6, c = i & 63;
        sP[i] = sP[i] * invmu - ((r == c) ? 1.0f : 0.0f);
    }
    __syncthreads();

    const int r0 = (t >> 4) * 4;
    const int c0 = (t & 15) * 4;
    {
        float a[4][4] = {};
        for (int k = 0; k < 64; ++k) {
            float pa[4], pb[4];
            #pragma unroll
            for (int i = 0; i < 4; ++i) pa[i] = sP[(r0 + i) * 64 + k];
            #pragma unroll
            for (int j = 0; j < 4; ++j) pb[j] = sP[k * 64 + c0 + j];
            #pragma unroll
            for (int i = 0; i < 4; ++i)
                #pragma unroll
                for (int j = 0; j < 4; ++j) a[i][j] += pa[i] * pb[j];
        }
        #pragma unroll
        for (int i = 0; i < 4; ++i)
            #pragma unroll
            for (int j = 0; j < 4; ++j) sQ[(r0 + i) * 64 + c0 + j] = a[i][j];
    }
    __syncthreads();

    const float rs = sRs;
    {
        float a[4][4] = {};  // Q@P block
        for (int k = 0; k < 64; ++k) {
            float pa[4], pb[4];
            #pragma unroll
            for (int i = 0; i < 4; ++i) pa[i] = sQ[(r0 + i) * 64 + k];
            #pragma unroll
            for (int j = 0; j < 4; ++j) pb[j] = sP[k * 64 + c0 + j];
            #pragma unroll
            for (int i = 0; i < 4; ++i)
                #pragma unroll
                for (int j = 0; j < 4; ++j) a[i][j] += pa[i] * pb[j];
        }
        #pragma unroll
        for (int i = 0; i < 4; ++i) {
            #pragma unroll
            for (int j = 0; j < 4; ++j) {
                int idx = (r0 + i) * 64 + (c0 + j);
                float dlt = (r0 + i == c0 + j) ? 1.0f : 0.0f;
                float wmh = dlt - 0.5f * sP[idx] + 0.375f * sQ[idx] - 0.3125f * a[i][j];
                g_E[idx] = __float2bfloat16(wmh * rs - dlt);
            }
        }
    }
}

// ---------------------------------------------------------------------------
// Kernel 4: whiten  out = xc + E @ xc   (persistent grid, 3 CTAs/SM; R10 form)
// ---------------------------------------------------------------------------
__global__ __launch_bounds__(256, 3) void whiten_kernel(const float* __restrict__ X,
                                                        float* __restrict__ Y) {
    __shared__ __nv_bfloat16  tb[2][NC * BPITCH];      // bf16 centered tiles
    __shared__ float          scratch[8][16 * SPITCH]; // per-warp 16x32 corr
    __shared__ float          smean[NC];

    const int t = threadIdx.x, b = blockIdx.x;
    const int warp = t >> 5, lane = t & 31;

    if (t < NC) smean[t] = g_mean[t];
    __syncthreads();

    const int r0 = (warp >> 1) * 16;       // warp's output channel strip
    const int q0 = (warp & 1) * 32;        // warp's s base
    const int row  = r0 + (lane >> 1);     // this lane's channel row
    const int coff = q0 + (lane & 1) * 4;  // this lane's first float col
    const float mu = smean[row];

    wmma::fragment<wmma::matrix_a, 16, 16, 16, __nv_bfloat16, wmma::row_major> fa[4];
    #pragma unroll
    for (int k = 0; k < 4; ++k)
        wmma::load_matrix_sync(fa[k], &g_E[r0 * 64 + k * 16], 64);

    const float* scp = &scratch[warp][(lane >> 1) * SPITCH + (lane & 1) * 4];

    // prologue: tile b -> centered regs + tb[0]
    float4 cur[4];
    {
        const int n  = b / 49;
        const int s0 = (b % 49) * KT;
        const float* src = X + (size_t)n * NC * SS + (size_t)row * SS + s0 + coff;
        #pragma unroll
        for (int j = 0; j < 4; ++j) {
            float4 v = *(const float4*)(src + 8 * j);
            v.x -= mu; v.y -= mu; v.z -= mu; v.w -= mu;
            cur[j] = v;
            __nv_bfloat162* dst = (__nv_bfloat162*)&tb[0][row * BPITCH + coff + 8 * j];
            dst[0] = __floats2bfloat162_rn(v.x, v.y);
            dst[1] = __floats2bfloat162_rn(v.z, v.w);
        }
    }
    __syncthreads();

    int buf = 0;
    for (int T = b; T < TILES; T += GRID_W, buf ^= 1) {
        const int n  = T / 49;
        const int s0 = (T % 49) * KT;

        wmma::fragment<wmma::accumulator, 16, 16, 16, float> acc0, acc1;
        wmma::fill_fragment(acc0, 0.0f);
        wmma::fill_fragment(acc1, 0.0f);
        #pragma unroll
        for (int k = 0; k < 4; ++k) {
            wmma::fragment<wmma::matrix_b, 16, 16, 16, __nv_bfloat16, wmma::row_major> fb0, fb1;
            wmma::load_matrix_sync(fb0, &tb[buf][(k * 16) * BPITCH + q0], BPITCH);
            wmma::load_matrix_sync(fb1, &tb[buf][(k * 16) * BPITCH + q0 + 16], BPITCH);
            wmma::mma_sync(acc0, fa[k], fb0, acc0);
            wmma::mma_sync(acc1, fa[k], fb1, acc1);
        }
        wmma::store_matrix_sync(&scratch[warp][0],  acc0, SPITCH, wmma::mem_row_major);
        wmma::store_matrix_sync(&scratch[warp][16], acc1, SPITCH, wmma::mem_row_major);
        __syncwarp();

        // epilogue (warp-local): out = xc(regs) + corr(scratch)
        {
            float* Yp = Y + (size_t)n * NC * SS + (size_t)row * SS + s0 + coff;
            #pragma unroll
            for (int j = 0; j < 4; ++j) {
                float4 c = *(const float4*)(scp + 8 * j);
                c.x += cur[j].x; c.y += cur[j].y; c.z += cur[j].z; c.w += cur[j].w;
                *(float4*)(Yp + 8 * j) = c;
            }
        }

        // load + center + publish next tile (acc regs dead -> reused)
        const int Tn = T + GRID_W;
        if (Tn < TILES) {
            const int nn = Tn / 49;
            const int sn = (Tn % 49) * KT;
            const float* src = X + (size_t)nn * NC * SS + (size_t)row * SS + sn + coff;
            #pragma unroll
            for (int j = 0; j < 4; ++j) {
                float4 v = *(const float4*)(src + 8 * j);
                v.x -= mu; v.y -= mu; v.z -= mu; v.w -= mu;
                cur[j] = v;
                __nv_bfloat162* dst = (__nv_bfloat162*)&tb[buf ^ 1][row * BPITCH + coff + 8 * j];
                dst[0] = __floats2bfloat162_rn(v.x, v.y);
                dst[1] = __floats2bfloat162_rn(v.z, v.w);
            }
        }
        __syncthreads();
    }
}

// ---------------------------------------------------------------------------
extern "C" void kernel_launch(void* const* d_in, const int* in_sizes, int n_in,
                              void* d_out, int out_size) {
    (void)in_sizes; (void)n_in; (void)out_size;
    const float* X = (const float*)d_in[0];
    float* Y = (float*)d_out;

    gram_kernel<<<GRID_G, 256>>>(X);
    reduce_kernel<<<5, 256>>>();
    stats_kernel<<<1, 256>>>();
    whiten_kernel<<<GRID_W, 256>>>(X, Y);
}

// round 14
// speedup vs baseline: 1.0837x; 1.0292x over previous
#include <cuda_runtime.h>
#include <cuda_bf16.h>
#include <mma.h>

using namespace nvcuda;

// Problem constants
#define NC     64          // channels
#define SS     3136        // 56*56
#define NIMG   128
#define MTOT   (NIMG*SS)   // 401408
#define KT     64          // s-tile width (gram)
#define TILES  (NIMG*49)   // 6272 tiles of 64 columns (gram)
#define GRID_G 296         // gram: one wave at 2 CTA/SM
#define GRID_W 296         // whiten: one wave at 2 CTA/SM
#define NWARPS (GRID_W*8)  // 2368 independent whiten warps
#define NSLICE (NIMG*196)  // 25088 slices of 64ch x 16s
#define BPITCH 72          // gram bf16 smem pitch
#define RPITCH 36          // gram reduction pitch
#define TPITCH 24          // whiten warp-tile bf16 pitch (48B rows)
#define SCP    20          // whiten warp scratch fp32 pitch
#define EPSF   1e-3f

// Scratch (static device globals: allocation-free)
__device__ float          g_partials[GRID_G][4160]; // 4096 gram + 64 channel sums
__device__ float          g_G[4160];
__device__ float          g_mean[NC];
__device__ __nv_bfloat16  g_E[NC*NC];               // wm - I, row-major [c_out][c_in]

// ---------------------------------------------------------------------------
// Kernel 1: partial Gram + channel sums (R11 form: split-K warps, register
// prefetch, double buffer, one barrier per tile).
// ---------------------------------------------------------------------------
__global__ __launch_bounds__(256, 2) void gram_kernel(const float* __restrict__ X) {
    __shared__ __nv_bfloat16 tb[2][NC * BPITCH];
    __shared__ float sred[4][32 * RPITCH];
    __shared__ float ssum[NC];

    const int t = threadIdx.x, b = blockIdx.x;
    const int warp = t >> 5;
    const int row = t >> 2;
    const int c4  = (t & 3) * 4;

    const int khalf = warp >> 2;
    const int quad  = warp & 3;
    const int r0 = (quad >> 1) * 32;
    const int q0 = (quad & 1) * 32;
    const int k0 = khalf * 32;

    wmma::fragment<wmma::accumulator, 16, 16, 16, float> acc[2][2];
    #pragma unroll
    for (int i = 0; i < 2; ++i)
        #pragma unroll
        for (int j = 0; j < 2; ++j)
            wmma::fill_fragment(acc[i][j], 0.0f);

    float lsum = 0.0f;

    {
        const int n  = b / 49;
        const int s0 = (b % 49) * KT;
        const float4* src = (const float4*)(X + (size_t)n * NC * SS + (size_t)row * SS + s0);
        #pragma unroll
        for (int j = 0; j < 4; ++j) {
            float4 v = src[c4 + j];
            lsum += v.x + v.y + v.z + v.w;
            __nv_bfloat162* dst = (__nv_bfloat162*)&tb[0][row * BPITCH + (c4 + j) * 4];
            dst[0] = __floats2bfloat162_rn(v.x, v.y);
            dst[1] = __floats2bfloat162_rn(v.z, v.w);
        }
    }
    __syncthreads();

    int buf = 0;
    for (int T = b; T < TILES; T += GRID_G, buf ^= 1) {
        const int Tn = T + GRID_G;
        const bool has = (Tn < TILES);

        float4 w[4];
        if (has) {
            const int n  = Tn / 49;
            const int s0 = (Tn % 49) * KT;
            const float4* src = (const float4*)(X + (size_t)n * NC * SS + (size_t)row * SS + s0);
            #pragma unroll
            for (int j = 0; j < 4; ++j) w[j] = src[c4 + j];
        }

        #pragma unroll
        for (int k = 0; k < 2; ++k) {
            const int kk = k0 + k * 16;
            wmma::fragment<wmma::matrix_a, 16, 16, 16, __nv_bfloat16, wmma::row_major> fa0, fa1;
            wmma::fragment<wmma::matrix_b, 16, 16, 16, __nv_bfloat16, wmma::col_major> fb0, fb1;
            wmma::load_matrix_sync(fa0, &tb[buf][(r0)      * BPITCH + kk], BPITCH);
            wmma::load_matrix_sync(fa1, &tb[buf][(r0 + 16) * BPITCH + kk], BPITCH);
            wmma::load_matrix_sync(fb0, &tb[buf][(q0)      * BPITCH + kk], BPITCH);
            wmma::load_matrix_sync(fb1, &tb[buf][(q0 + 16) * BPITCH + kk], BPITCH);
            wmma::mma_sync(acc[0][0], fa0, fb0, acc[0][0]);
            wmma::mma_sync(acc[0][1], fa0, fb1, acc[0][1]);
            wmma::mma_sync(acc[1][0], fa1, fb0, acc[1][0]);
            wmma::mma_sync(acc[1][1], fa1, fb1, acc[1][1]);
        }

        if (has) {
            #pragma unroll
            for (int j = 0; j < 4; ++j) {
                lsum += w[j].x + w[j].y + w[j].z + w[j].w;
                __nv_bfloat162* dst = (__nv_bfloat162*)&tb[buf ^ 1][row * BPITCH + (c4 + j) * 4];
                dst[0] = __floats2bfloat162_rn(w[j].x, w[j].y);
                dst[1] = __floats2bfloat162_rn(w[j].z, w[j].w);
            }
        }
        __syncthreads();
    }

    lsum += __shfl_down_sync(0xffffffffu, lsum, 2);
    lsum += __shfl_down_sync(0xffffffffu, lsum, 1);
    if ((t & 3) == 0) ssum[row] = lsum;

    if (khalf == 1) {
        #pragma unroll
        for (int i = 0; i < 2; ++i)
            #pragma unroll
            for (int j = 0; j < 2; ++j)
                wmma::store_matrix_sync(&sred[quad][(16 * i) * RPITCH + 16 * j],
                                        acc[i][j], RPITCH, wmma::mem_row_major);
    }
    __syncthreads();

    if (khalf == 0) {
        #pragma unroll
        for (int i = 0; i < 2; ++i) {
            #pragma unroll
            for (int j = 0; j < 2; ++j) {
                wmma::fragment<wmma::accumulator, 16, 16, 16, float> tmp;
                wmma::load_matrix_sync(tmp, &sred[quad][(16 * i) * RPITCH + 16 * j],
                                       RPITCH, wmma::mem_row_major);
                #pragma unroll
                for (int e = 0; e < tmp.num_elements; ++e)
                    acc[i][j].x[e] += tmp.x[e];
                wmma::store_matrix_sync(&g_partials[b][(r0 + 16 * i) * 64 + q0 + 16 * j],
                                        acc[i][j], 64, wmma::mem_row_major);
            }
        }
    }
    if (t < NC) g_partials[b][4096 + t] = ssum[t];
}

// ---------------------------------------------------------------------------
// Kernel 2: reduce GRID_G partials -> g_G  (float4 vectorized)
// ---------------------------------------------------------------------------
__global__ __launch_bounds__(256) void reduce_kernel() {
    const int i4 = blockIdx.x * blockDim.x + threadIdx.x;
    if (i4 < 1040) {
        float4 s = make_float4(0.f, 0.f, 0.f, 0.f);
        #pragma unroll 4
        for (int b = 0; b < GRID_G; ++b) {
            float4 v = ((const float4*)g_partials[b])[i4];
            s.x += v.x; s.y += v.y; s.z += v.z; s.w += v.w;
        }
        ((float4*)g_G)[i4] = s;
    }
}

// ---------------------------------------------------------------------------
// Kernel 3: single-block stats: sigma -> Taylor inverse-sqrt -> E = wm - I
// ---------------------------------------------------------------------------
__global__ __launch_bounds__(256) void stats_kernel() {
    __shared__ float sP[4096];
    __shared__ float sQ[4096];
    __shared__ float smean[NC];
    __shared__ float sMu, sRs;

    const int t = threadIdx.x;
    const float invm = 1.0f / (float)MTOT;

    if (t < NC) {
        float mn = g_G[4096 + t] * invm;
        smean[t] = mn;
        g_mean[t] = mn;
    }
    __syncthreads();

    for (int i = t; i < 4096; i += 256) {
        int r = i >> 6, c = i & 63;
        sP[i] = g_G[i] * invm - smean[r] * smean[c] + ((r == c) ? EPSF : 0.0f);
    }
    __syncthreads();

    if (t == 0) {
        float tr = 0.0f;
        for (int i = 0; i < NC; ++i) tr += sP[i * 65];
        float mu = tr / (float)NC;
        sMu = mu;
        float rs = rsqrtf(mu);
        rs = rs * (1.5f - 0.5f * mu * rs * rs);
        sRs = rs;
    }
    __syncthreads();

    const float invmu = 1.0f / sMu;
    for (int i = t; i < 4096; i += 256) {
        int r = i >> 6, c = i & 63;
        sP[i] = sP[i] * invmu - ((r == c) ? 1.0f : 0.0f);
    }
    __syncthreads();

    const int r0 = (t >> 4) * 4;
    const int c0 = (t & 15) * 4;
    {
        float a[4][4] = {};
        for (int k = 0; k < 64; ++k) {
            float pa[4], pb[4];
            #pragma unroll
            for (int i = 0; i < 4; ++i) pa[i] = sP[(r0 + i) * 64 + k];
            #pragma unroll
            for (int j = 0; j < 4; ++j) pb[j] = sP[k * 64 + c0 + j];
            #pragma unroll
            for (int i = 0; i < 4; ++i)
                #pragma unroll
                for (int j = 0; j < 4; ++j) a[i][j] += pa[i] * pb[j];
        }
        #pragma unroll
        for (int i = 0; i < 4; ++i)
            #pragma unroll
            for (int j = 0; j < 4; ++j) sQ[(r0 + i) * 64 + c0 + j] = a[i][j];
    }
    __syncthreads();

    const float rs = sRs;
    {
        float a[4][4] = {};
        for (int k = 0; k < 64; ++k) {
            float pa[4], pb[4];
            #pragma unroll
            for (int i = 0; i < 4; ++i) pa[i] = sQ[(r0 + i) * 64 + k];
            #pragma unroll
            for (int j = 0; j < 4; ++j) pb[j] = sP[k * 64 + c0 + j];
            #pragma unroll
            for (int i = 0; i < 4; ++i)
                #pragma unroll
                for (int j = 0; j < 4; ++j) a[i][j] += pa[i] * pb[j];
        }
        #pragma unroll
        for (int i = 0; i < 4; ++i) {
            #pragma unroll
            for (int j = 0; j < 4; ++j) {
                int idx = (r0 + i) * 64 + (c0 + j);
                float dlt = (r0 + i == c0 + j) ? 1.0f : 0.0f;
                float wmh = dlt - 0.5f * sP[idx] + 0.375f * sQ[idx] - 0.3125f * a[i][j];
                g_E[idx] = __float2bfloat16(wmh * rs - dlt);
            }
        }
    }
}

// ---------------------------------------------------------------------------
// Kernel 4: whiten, warp-independent. out^T = xc^T @ E^T  (+ fp32 identity).
// Each warp owns 64ch x 16s slices end-to-end. FIX vs R12: the loader now
// covers ALL 64 channels (4 passes of 16, c = cl + bi*16). No block barriers.
// ---------------------------------------------------------------------------
__global__ __launch_bounds__(256, 2) void whiten_kernel(const float* __restrict__ X,
                                                        float* __restrict__ Y) {
    __shared__ __align__(16) char wsm[8][4608];   // per-warp: bf16 tile(3KB) + scratch(1.28KB)
    __shared__ float smean[NC];

    const int t = threadIdx.x, b = blockIdx.x;
    const int warp = t >> 5, lane = t & 31;

    if (t < NC) smean[t] = g_mean[t];
    __syncthreads();   // the only block barrier

    __nv_bfloat16* tile = (__nv_bfloat16*)wsm[warp];
    float*         scr  = (float*)(wsm[warp] + 3072);

    // hoisted E^T fragments: B(k=c_in, n=c_out) = g_E[n*64+k] -> col_major ld=64
    wmma::fragment<wmma::matrix_b, 16, 16, 16, __nv_bfloat16, wmma::col_major> fb[4][4];
    #pragma unroll
    for (int kb = 0; kb < 4; ++kb)
        #pragma unroll
        for (int nb = 0; nb < 4; ++nb)
            wmma::load_matrix_sync(fb[kb][nb], &g_E[(nb * 16) * 64 + kb * 16], 64);

    const int cl = lane >> 1;        // 0..15
    const int o  = lane & 1;         // float4 selector within 64B row
    float mus[4];
    #pragma unroll
    for (int bi = 0; bi < 4; ++bi) mus[bi] = smean[cl + bi * 16];

    const int W = b * 8 + warp;      // global warp id

    for (int S = W; S < NSLICE; S += NWARPS) {
        const int n  = S / 196;
        const int sc = (S % 196) * 16;
        const float* base = X + (size_t)n * NC * SS + sc;

        __syncwarp();  // previous slice fully drained before tile overwrite

        // load 64ch x 16s slice: lane pair covers one channel row (64B);
        // 4 passes cover all 64 channels
        float4 w[4][2];
        #pragma unroll
        for (int bi = 0; bi < 4; ++bi) {
            const float* p = base + (size_t)(cl + bi * 16) * SS;
            w[bi][0] = *(const float4*)(p + o * 4);
            w[bi][1] = *(const float4*)(p + o * 4 + 8);
        }
        // center + bf16 into warp tile
        #pragma unroll
        for (int bi = 0; bi < 4; ++bi) {
            const int c = cl + bi * 16;
            const float mu = mus[bi];
            #pragma unroll
            for (int q = 0; q < 2; ++q) {
                float4 v = w[bi][q];
                v.x -= mu; v.y -= mu; v.z -= mu; v.w -= mu;
                __nv_bfloat162* dst = (__nv_bfloat162*)&tile[c * TPITCH + o * 4 + q * 8];
                dst[0] = __floats2bfloat162_rn(v.x, v.y);
                dst[1] = __floats2bfloat162_rn(v.z, v.w);
            }
        }
        __syncwarp();

        // A = xc^T blocks (s x c_in) via col_major ldmatrix
        wmma::fragment<wmma::matrix_a, 16, 16, 16, __nv_bfloat16, wmma::col_major> fA[4];
        #pragma unroll
        for (int kb = 0; kb < 4; ++kb)
            wmma::load_matrix_sync(fA[kb], &tile[(kb * 16) * TPITCH], TPITCH);

        float* yb = Y + (size_t)n * NC * SS + sc;

        #pragma unroll
        for (int nb = 0; nb < 4; ++nb) {
            wmma::fragment<wmma::accumulator, 16, 16, 16, float> acc;
            wmma::fill_fragment(acc, 0.0f);
            #pragma unroll
            for (int kb = 0; kb < 4; ++kb)
                wmma::mma_sync(acc, fA[kb], fb[kb][nb], acc);
            // col_major store -> scr[c_local*SCP + s]  (channel-major rows)
            wmma::store_matrix_sync(scr, acc, SCP, wmma::mem_col_major);
            __syncwarp();

            // epilogue quarter: channels nb*16 .. nb*16+15
            {
                const int c = nb * 16 + cl;
                const float mu = smean[c];
                const float* xp = base + (size_t)c * SS;
                float*       yp = yb   + (size_t)c * SS;
                #pragma unroll
                for (int q = 0; q < 2; ++q) {
                    const int off = o * 4 + q * 8;
                    float4 xv = *(const float4*)(xp + off);     // L1-hot
                    float4 cv = *(const float4*)(scr + cl * SCP + off);
                    xv.x = xv.x - mu + cv.x;
                    xv.y = xv.y - mu + cv.y;
                    xv.z = xv.z - mu + cv.z;
                    xv.w = xv.w - mu + cv.w;
                    *(float4*)(yp + off) = xv;
                }
            }
            __syncwarp();
        }
    }
}

// ---------------------------------------------------------------------------
extern "C" void kernel_launch(void* const* d_in, const int* in_sizes, int n_in,
                              void* d_out, int out_size) {
    (void)in_sizes; (void)n_in; (void)out_size;
    const float* X = (const float*)d_in[0];
    float* Y = (float*)d_out;

    gram_kernel<<<GRID_G, 256>>>(X);
    reduce_kernel<<<5, 256>>>();
    stats_kernel<<<1, 256>>>();
    whiten_kernel<<<GRID_W, 256>>>(X, Y);
}